// round 3
// baseline (speedup 1.0000x reference)
#include <cuda_runtime.h>
#include <math.h>

// Problem dims
#define BB   2
#define CCH  16
#define HH   128
#define WW   128
#define MM   9
#define NDD  9
#define MCC  144
#define HIDN 18
#define OUTC 150
#define HWD  (HH*WW*NDD)   // 147456
#define EPSBN 1e-5f

// Scratch (device globals; no runtime allocation allowed)
__device__ float g_cv [BB*(size_t)MCC*HWD];   // cost volume  [b][mc][h][w][d]
__device__ float g_h1 [BB*(size_t)HIDN*HWD];  // hidden
__device__ float g_wei[BB*(size_t)MM*HWD];    // sigmoid attention
__device__ float g_p  [BB*MCC];               // global mean pool
__device__ float g_xg [BB*MM];                // global-branch logits
__device__ float g_w1p[6*MCC*27*6];           // conv1 w dup-packed [g][mc][tap][2*3oc]
__device__ float g_w2p[3*HIDN*27*6];          // conv2 w dup-packed [g][ci][tap][2*3oc]

typedef unsigned long long u64;

__device__ __forceinline__ u64 pk2(float lo, float hi) {
    u64 r;
    asm("mov.b64 %0, {%1, %2};" : "=l"(r) : "r"(__float_as_uint(lo)), "r"(__float_as_uint(hi)));
    return r;
}
__device__ __forceinline__ void upk2(float &lo, float &hi, u64 v) {
    unsigned a, b;
    asm("mov.b64 {%0, %1}, %2;" : "=r"(a), "=r"(b) : "l"(v));
    lo = __uint_as_float(a); hi = __uint_as_float(b);
}
__device__ __forceinline__ void fma2(u64 &d, u64 a, u64 b) {
    asm("fma.rn.f32x2 %0, %1, %2, %0;" : "+l"(d) : "l"(a), "l"(b));
}

// ---------------------------------------------------------------------------
// K1: build cost volume AND mean-pool it in one pass.
// One block per (b,mc) slice. Deterministic tree reduction.
// ---------------------------------------------------------------------------
__global__ __launch_bounds__(256) void k_build_reduce(const float* __restrict__ x) {
    int bm = blockIdx.x;                 // 0..287
    int b = bm / MCC, mc = bm % MCC;
    int m = mc / CCH, c = mc % CCH;
    const float* xb = x + ((size_t)(b*CCH + c)*HH*WW)*MM + m;
    float* dst = g_cv + (size_t)bm * HWD;
    int sh_d = m - 4;
    float s = 0.f;
    for (int i = threadIdx.x; i < HWD; i += 256) {
        int d = i % NDD;
        int w = (i / NDD) % WW;
        int h = i / (NDD*WW);
        int ws = w + (d - 4) * sh_d;
        float v = 0.f;
        if ((unsigned)ws < WW) v = xb[(size_t)(h*WW + ws)*MM];
        dst[i] = v;
        s += v;
    }
    __shared__ float sh[256];
    sh[threadIdx.x] = s;
    __syncthreads();
    for (int o = 128; o > 0; o >>= 1) {
        if (threadIdx.x < o) sh[threadIdx.x] += sh[threadIdx.x + o];
        __syncthreads();
    }
    if (threadIdx.x == 0) g_p[bm] = sh[0] * (1.0f / HWD);
}

// ---------------------------------------------------------------------------
// K3: global attention branch (center tap only at 1x1x1 spatial).
// ---------------------------------------------------------------------------
__global__ void k_global(const float* __restrict__ w1, const float* __restrict__ b1,
                         const float* __restrict__ g1, const float* __restrict__ be1,
                         const float* __restrict__ m1, const float* __restrict__ v1,
                         const float* __restrict__ w2, const float* __restrict__ b2,
                         const float* __restrict__ g2, const float* __restrict__ be2,
                         const float* __restrict__ m2, const float* __restrict__ v2) {
    __shared__ float gh[BB*HIDN];
    int t = threadIdx.x;
    if (t < BB*HIDN) {
        int b = t / HIDN, o = t % HIDN;
        float s = b1[o];
        for (int c = 0; c < MCC; c++)
            s += w1[(o*MCC + c)*27 + 13] * g_p[b*MCC + c];
        float sc = g1[o] * rsqrtf(v1[o] + EPSBN);
        s = (s - m1[o]) * sc + be1[o];
        gh[t] = fmaxf(s, 0.f);
    }
    __syncthreads();
    if (t < BB*MM) {
        int b = t / MM, og = t % MM;
        float s = b2[og];
        for (int o = 0; o < HIDN; o++)
            s += w2[(og*HIDN + o)*27 + 13] * gh[b*HIDN + o];
        float sc = g2[og] * rsqrtf(v2[og] + EPSBN);
        g_xg[t] = (s - m2[og]) * sc + be2[og];
    }
}

// ---------------------------------------------------------------------------
// K-pack: duplicate conv weights into {w,w} pairs, 3-oc groups.
// ---------------------------------------------------------------------------
__global__ void k_packw(const float* __restrict__ w1, const float* __restrict__ w2) {
    int t = blockIdx.x * 256 + threadIdx.x;
    if (t < HIDN*MCC*27) {
        int oc = t / (MCC*27); int r = t % (MCC*27);
        int mc = r / 27, tap = r % 27;
        int g = oc / 3, o = oc % 3;
        float v = w1[((size_t)oc*MCC + mc)*27 + tap];
        float* d = &g_w1p[((size_t)(g*MCC + mc)*27 + tap)*6 + 2*o];
        d[0] = v; d[1] = v;
    }
    if (t < MM*HIDN*27) {
        int oc = t / (HIDN*27); int r = t % (HIDN*27);
        int ci = r / 27, tap = r % 27;
        int g = oc / 3, o = oc % 3;
        float v = w2[((size_t)oc*HIDN + ci)*27 + tap];
        float* d = &g_w2p[((size_t)(g*HIDN + ci)*27 + tap)*6 + 2*o];
        d[0] = v; d[1] = v;
    }
}

// ---------------------------------------------------------------------------
// K4/K5: 3x3x3 conv, 3 oc x 9 d per thread, f32x2 packed over d.
// Block 128 = 16(w) x 8(h) pixels. grid z = B * NOCG (3 oc per group).
// Tile smem: [MCH][10h][18w][12z], z = d+1 (z 0,10,11 stay zero).
// ---------------------------------------------------------------------------
template<int CIN, int MCH, int NOCG, int OCTOT, bool FIRST>
__global__ __launch_bounds__(128) void k_conv(
        const float* __restrict__ gam, const float* __restrict__ bet,
        const float* __restrict__ mu,  const float* __restrict__ var,
        const float* __restrict__ bias) {
    __shared__ float tile[MCH*10*18*12];
    __shared__ float wsh[MCH*27*6];

    const float* src = FIRST ? g_cv : g_h1;
    const float* wpk = FIRST ? g_w1p : g_w2p;
    float* dst       = FIRST ? g_h1 : g_wei;

    int tid = threadIdx.x;
    int tx = tid & 15, ty = tid >> 4;        // 16 x 8
    int gz = blockIdx.z;
    int b = gz / NOCG, g = gz % NOCG;
    int w0 = blockIdx.x * 16, h0 = blockIdx.y * 8;

    for (int i = tid; i < MCH*10*18*12; i += 128) tile[i] = 0.f;

    u64 acc[3][5];
#pragma unroll
    for (int o = 0; o < 3; o++)
#pragma unroll
        for (int p = 0; p < 5; p++) acc[o][p] = 0ull;

    const float* srcb = src + (size_t)b*CIN*HWD;
    const float* wg   = wpk + (size_t)g*CIN*27*6;

    for (int c0 = 0; c0 < CIN; c0 += MCH) {
        __syncthreads();
        for (int i = tid; i < MCH*27*6; i += 128)
            wsh[i] = wg[(size_t)c0*27*6 + i];
        for (int i = tid; i < MCH*10*18*9; i += 128) {
            int d = i % 9; int r = i / 9;
            int wi = r % 18; r /= 18;
            int hi = r % 10; int mcl = r / 10;
            int h = h0 - 1 + hi, w = w0 - 1 + wi;
            float v = 0.f;
            if ((unsigned)h < HH && (unsigned)w < WW)
                v = srcb[(size_t)(c0 + mcl)*HWD + (h*WW + w)*9 + d];
            tile[((mcl*10 + hi)*18 + wi)*12 + d + 1] = v;
        }
        __syncthreads();
#pragma unroll 1
        for (int mcl = 0; mcl < MCH; mcl++) {
            const float* tb = tile + mcl*10*18*12;
            const u64*   wb = (const u64*)(wsh + mcl*27*6);
#pragma unroll
            for (int k0 = 0; k0 < 3; k0++)
#pragma unroll
            for (int k1 = 0; k1 < 3; k1++) {
                const float4* tp = (const float4*)(tb + ((ty + k0)*18 + (tx + k1))*12);
                float4 q0 = tp[0], q1 = tp[1], q2 = tp[2];
                float t[12] = {q0.x,q0.y,q0.z,q0.w, q1.x,q1.y,q1.z,q1.w,
                               q2.x,q2.y,q2.z,q2.w};
                u64 E[6], O[5];
#pragma unroll
                for (int p = 0; p < 6; p++) E[p] = pk2(t[2*p], t[2*p + 1]);
#pragma unroll
                for (int p = 0; p < 5; p++) O[p] = pk2(t[2*p + 1], t[2*p + 2]);
                const u64* wr = wb + (k0*3 + k1)*9;   // 3 k2 x 3 oc
#pragma unroll
                for (int o = 0; o < 3; o++) {
                    u64 wv = wr[o];                   // k2 = 0
#pragma unroll
                    for (int p = 0; p < 5; p++) fma2(acc[o][p], wv, E[p]);
                }
#pragma unroll
                for (int o = 0; o < 3; o++) {
                    u64 wv = wr[3 + o];               // k2 = 1
#pragma unroll
                    for (int p = 0; p < 5; p++) fma2(acc[o][p], wv, O[p]);
                }
#pragma unroll
                for (int o = 0; o < 3; o++) {
                    u64 wv = wr[6 + o];               // k2 = 2
#pragma unroll
                    for (int p = 0; p < 5; p++) fma2(acc[o][p], wv, E[p + 1]);
                }
            }
        }
    }

    int h = h0 + ty, w = w0 + tx;
#pragma unroll
    for (int o = 0; o < 3; o++) {
        int oc = g*3 + o;
        float s  = gam[oc] * rsqrtf(var[oc] + EPSBN);
        float bi = (bias[oc] - mu[oc]) * s + bet[oc];
        float xg = FIRST ? 0.f : g_xg[b*MM + oc];
        float* dp = dst + (size_t)(b*OCTOT + oc)*HWD + (h*WW + w)*9;
#pragma unroll
        for (int p = 0; p < 5; p++) {
            float lo, hi;
            upk2(lo, hi, acc[o][p]);
            float y0 = lo*s + bi;
            if (FIRST) y0 = fmaxf(y0, 0.f);
            else       y0 = 1.f / (1.f + expf(-(y0 + xg)));
            dp[2*p] = y0;
            if (p < 4) {
                float y1 = hi*s + bi;
                if (FIRST) y1 = fmaxf(y1, 0.f);
                else       y1 = 1.f / (1.f + expf(-(y1 + xg)));
                dp[2*p + 1] = y1;
            }
        }
    }
}

// ---------------------------------------------------------------------------
// K6: conv_last GEMM, A computed on-the-fly (cv LDG.128 * wei reg tile).
// smem: Ws [144][162] + weis [9][128]. Thread: 10 oc-pairs x 4 p.
// ---------------------------------------------------------------------------
extern __shared__ float sfin[];
__global__ __launch_bounds__(256) void k_final(
        const float* __restrict__ clw, const float* __restrict__ clb,
        float* __restrict__ out) {
    float* Ws   = sfin;               // [144][162] (oc >= 150 zero)
    float* weis = sfin + 144*162;     // [9][128]
    int b  = blockIdx.y;
    int p0 = blockIdx.x * 128;
    int tid = threadIdx.x;

    for (int t = tid; t < 162*144; t += 256) {
        int oc = t / 144, k = t % 144;          // k-coalesced LDG
        Ws[k*162 + oc] = (oc < OUTC) ? clw[oc*MCC + k] : 0.f;
    }
    const float* wb = g_wei + (size_t)b*MM*HWD + p0;
    for (int t = tid; t < 9*128; t += 256) {
        int c = t >> 7, p = t & 127;
        weis[t] = wb[(size_t)c*HWD + p];
    }
    __syncthreads();

    int tx = tid & 31, ty = tid >> 5;
    u64 acc[10][4];
#pragma unroll
    for (int j = 0; j < 10; j++)
#pragma unroll
        for (int i = 0; i < 4; i++) acc[j][i] = 0ull;

    const float* cvb = g_cv + (size_t)b*MCC*HWD + p0 + tx*4;

    for (int kg = 0; kg < 9; kg++) {
        float4 wr4 = *(const float4*)(weis + kg*128 + tx*4);
#pragma unroll
        for (int kk = 0; kk < 16; kk++) {
            int k = kg*16 + kk;
            float4 cvv = *(const float4*)(cvb + (size_t)k*HWD);
            u64 a0 = pk2(cvv.x*wr4.x, cvv.x*wr4.x);
            u64 a1 = pk2(cvv.y*wr4.y, cvv.y*wr4.y);
            u64 a2 = pk2(cvv.z*wr4.z, cvv.z*wr4.z);
            u64 a3 = pk2(cvv.w*wr4.w, cvv.w*wr4.w);
            const u64* wrow = (const u64*)(Ws + k*162) + ty*10;
#pragma unroll
            for (int j = 0; j < 10; j++) {
                u64 wv = wrow[j];
                fma2(acc[j][0], wv, a0); fma2(acc[j][1], wv, a1);
                fma2(acc[j][2], wv, a2); fma2(acc[j][3], wv, a3);
            }
        }
    }

#pragma unroll
    for (int j = 0; j < 10; j++) {
        int oc0 = ty*20 + 2*j;
        float lo[4], hi[4];
#pragma unroll
        for (int i = 0; i < 4; i++) upk2(lo[i], hi[i], acc[j][i]);
        if (oc0 < OUTC) {
            float bv = clb[oc0];
            float4 r = make_float4(lo[0]+bv, lo[1]+bv, lo[2]+bv, lo[3]+bv);
            *(float4*)(out + (size_t)(b*OUTC + oc0)*HWD + p0 + tx*4) = r;
        }
        if (oc0 + 1 < OUTC) {
            float bv = clb[oc0+1];
            float4 r = make_float4(hi[0]+bv, hi[1]+bv, hi[2]+bv, hi[3]+bv);
            *(float4*)(out + (size_t)(b*OUTC + oc0 + 1)*HWD + p0 + tx*4) = r;
        }
    }
}

// ---------------------------------------------------------------------------
extern "C" void kernel_launch(void* const* d_in, const int* in_sizes, int n_in,
                              void* d_out, int out_size) {
    const float* x      = (const float*)d_in[0];
    const float* la_w1  = (const float*)d_in[1];
    const float* la_b1  = (const float*)d_in[2];
    const float* la_g1  = (const float*)d_in[3];
    const float* la_be1 = (const float*)d_in[4];
    const float* la_m1  = (const float*)d_in[5];
    const float* la_v1  = (const float*)d_in[6];
    const float* la_w2  = (const float*)d_in[7];
    const float* la_b2  = (const float*)d_in[8];
    const float* la_g2  = (const float*)d_in[9];
    const float* la_be2 = (const float*)d_in[10];
    const float* la_m2  = (const float*)d_in[11];
    const float* la_v2  = (const float*)d_in[12];
    const float* ga_w1  = (const float*)d_in[13];
    const float* ga_b1  = (const float*)d_in[14];
    const float* ga_g1  = (const float*)d_in[15];
    const float* ga_be1 = (const float*)d_in[16];
    const float* ga_m1  = (const float*)d_in[17];
    const float* ga_v1  = (const float*)d_in[18];
    const float* ga_w2  = (const float*)d_in[19];
    const float* ga_b2  = (const float*)d_in[20];
    const float* ga_g2  = (const float*)d_in[21];
    const float* ga_be2 = (const float*)d_in[22];
    const float* ga_m2  = (const float*)d_in[23];
    const float* ga_v2  = (const float*)d_in[24];
    const float* cl_w   = (const float*)d_in[25];
    const float* cl_b   = (const float*)d_in[26];
    float* out = (float*)d_out;

    k_build_reduce<<<BB*MCC, 256>>>(x);
    k_global<<<1, 64>>>(ga_w1, ga_b1, ga_g1, ga_be1, ga_m1, ga_v1,
                        ga_w2, ga_b2, ga_g2, ga_be2, ga_m2, ga_v2);
    k_packw<<<(HIDN*MCC*27 + 255)/256, 256>>>(la_w1, la_w2);

    dim3 g1(WW/16, HH/8, BB*6);
    k_conv<MCC, 4, 6, 18, true><<<g1, 128>>>(la_g1, la_be1, la_m1, la_v1, la_b1);
    dim3 g2(WW/16, HH/8, BB*3);
    k_conv<HIDN, 3, 3, 9, false><<<g2, 128>>>(la_g2, la_be2, la_m2, la_v2, la_b2);

    const int smem_fin = (144*162 + 9*128) * 4;   // 97920
    cudaFuncSetAttribute(k_final, cudaFuncAttributeMaxDynamicSharedMemorySize, smem_fin);
    dim3 gf(HWD/128, BB);
    k_final<<<gf, 256, smem_fin>>>(cl_w, cl_b, out);
}